// round 1
// baseline (speedup 1.0000x reference)
#include <cuda_runtime.h>
#include <math.h>

// Problem constants
#define VV 27
#define EE 64
#define HH 128
#define BB 256
#define SE 512
#define SD 512

// Scratch for decoder hidden states: [B, S_DEC, H] fp32 = 64 MB.
// __device__ global (module-load allocation) — permitted scratch mechanism.
__device__ float g_dec_h[(size_t)BB * SD * HH];

// =====================================================================
// Kernel 1: fused encoder+decoder scan.
// Grid: 128 CTAs x 256 threads. Each CTA owns 2 batch rows; threads
// 0-127 = row (2*bx), threads 128-255 = row (2*bx+1). Thread j computes
// hidden unit j. Wh column j lives in 128 registers. Token->xw tables
// (embed@Wx+b, only 27 rows!) built once per CTA into smem.
// =====================================================================
__global__ void __launch_bounds__(256) scan_kernel(
    const int*   __restrict__ enc_ids, const int* __restrict__ dec_ids,
    const float* __restrict__ embed,
    const float* __restrict__ enc_Wx, const float* __restrict__ enc_Wh,
    const float* __restrict__ enc_b,
    const float* __restrict__ dec_Wx, const float* __restrict__ dec_Wh,
    const float* __restrict__ dec_b)
{
    __shared__ float tabE[VV][HH];        // 13.5 KB
    __shared__ float tabD[VV][HH];        // 13.5 KB
    __shared__ float emb_s[VV * EE];      // 6.75 KB
    __shared__ float hbuf[2][2][HH];      // double-buffered h per row-group
    __shared__ int   idsE[2][SE];         // 4 KB
    __shared__ int   idsD[2][SD];         // 4 KB

    const int tid  = threadIdx.x;
    const int grp  = tid >> 7;            // which of the 2 rows
    const int j    = tid & (HH - 1);      // hidden unit
    const int row0 = blockIdx.x * 2;
    const int row  = row0 + grp;

    // ---- stage embeddings + token ids in smem (coalesced) ----
    for (int i = tid; i < VV * EE; i += 256) emb_s[i] = embed[i];
    for (int i = tid; i < SE; i += 256) {
        idsE[0][i] = enc_ids[(size_t)row0 * SE + i];
        idsE[1][i] = enc_ids[(size_t)(row0 + 1) * SE + i];
    }
    for (int i = tid; i < SD; i += 256) {
        idsD[0][i] = dec_ids[(size_t)row0 * SD + i];
        idsD[1][i] = dec_ids[(size_t)(row0 + 1) * SD + i];
    }
    __syncthreads();

    // ---- build token tables: tab[v][h] = sum_e emb[v][e]*Wx[e][h] + b[h] ----
    for (int idx = tid; idx < VV * HH; idx += 256) {
        const int v = idx / HH;
        const int h = idx - v * HH;
        float sE = enc_b[h];
        float sD = dec_b[h];
        #pragma unroll 8
        for (int e = 0; e < EE; e++) {
            const float em = emb_s[v * EE + e];
            sE = fmaf(em, enc_Wx[e * HH + h], sE);
            sD = fmaf(em, dec_Wx[e * HH + h], sD);
        }
        tabE[v][h] = sE;
        tabD[v][h] = sD;
    }

    // h0 = 0
    hbuf[0][grp][j] = 0.0f;
    __syncthreads();

    // ---- encoder phase: Wh column in registers ----
    float w[HH];
    #pragma unroll
    for (int k = 0; k < HH; k++) w[k] = enc_Wh[k * HH + j];

    int cur = 0;
    for (int t = 0; t < SE; t++) {
        const float4* hq = (const float4*)hbuf[cur][grp];
        float a0 = 0.f, a1 = 0.f, a2 = 0.f, a3 = 0.f;
        #pragma unroll
        for (int q = 0; q < HH / 4; q++) {
            const float4 hv = hq[q];        // smem broadcast, conflict-free
            a0 = fmaf(hv.x, w[4 * q + 0], a0);
            a1 = fmaf(hv.y, w[4 * q + 1], a1);
            a2 = fmaf(hv.z, w[4 * q + 2], a2);
            a3 = fmaf(hv.w, w[4 * q + 3], a3);
        }
        const int id = idsE[grp][t];
        const float hn = tanhf((a0 + a1) + (a2 + a3) + tabE[id][j]);
        hbuf[cur ^ 1][grp][j] = hn;
        // per-row-group named barrier: the two rows never couple
        asm volatile("bar.sync %0, 128;" :: "r"(grp + 1) : "memory");
        cur ^= 1;
    }

    // ---- decoder phase: reload Wh column, stream h to global scratch ----
    #pragma unroll
    for (int k = 0; k < HH; k++) w[k] = dec_Wh[k * HH + j];

    float* outrow = g_dec_h + (size_t)row * SD * HH;
    for (int t = 0; t < SD; t++) {
        const float4* hq = (const float4*)hbuf[cur][grp];
        float a0 = 0.f, a1 = 0.f, a2 = 0.f, a3 = 0.f;
        #pragma unroll
        for (int q = 0; q < HH / 4; q++) {
            const float4 hv = hq[q];
            a0 = fmaf(hv.x, w[4 * q + 0], a0);
            a1 = fmaf(hv.y, w[4 * q + 1], a1);
            a2 = fmaf(hv.z, w[4 * q + 2], a2);
            a3 = fmaf(hv.w, w[4 * q + 3], a3);
        }
        const int id = idsD[grp][t];
        const float hn = tanhf((a0 + a1) + (a2 + a3) + tabD[id][j]);
        hbuf[cur ^ 1][grp][j] = hn;
        outrow[t * HH + j] = hn;            // coalesced 512B store
        asm volatile("bar.sync %0, 128;" :: "r"(grp + 1) : "memory");
        cur ^= 1;
    }
}

// =====================================================================
// Kernel 2: logits = dec_h @ dense_W + dense_b.
// [131072, 128] x [128, 27]. CTA: 256 threads, 64 tokens.
// Thread = (v = tid&31 [27 live + 5 pad], token-group = tid>>5, 8 tokens).
// dense_W column v in 128 registers; h tile in smem (broadcast reads).
// =====================================================================
__global__ void __launch_bounds__(256) logits_kernel(
    const float* __restrict__ dense_W, const float* __restrict__ dense_b,
    float* __restrict__ out)
{
    __shared__ float hs[64 * HH];          // 32 KB token tile

    const int tid = threadIdx.x;
    const int v   = tid & 31;
    const int tg  = tid >> 5;              // 0..7, 8 tokens each
    const size_t tok0 = (size_t)blockIdx.x * 64;

    const float* hsrc = g_dec_h + tok0 * HH;
    for (int i = tid; i < 64 * HH; i += 256) hs[i] = hsrc[i];

    float wd[HH];
    const bool live = (v < VV);
    const float bias = live ? dense_b[v] : 0.0f;
    #pragma unroll
    for (int k = 0; k < HH; k++) wd[k] = live ? dense_W[k * VV + v] : 0.0f;
    __syncthreads();

    float acc[8];
    #pragma unroll
    for (int r = 0; r < 8; r++) acc[r] = bias;

    #pragma unroll
    for (int q = 0; q < HH / 4; q++) {
        #pragma unroll
        for (int r = 0; r < 8; r++) {
            const float4 hv =
                ((const float4*)(hs + (tg * 8 + r) * HH))[q];  // broadcast
            acc[r] = fmaf(hv.x, wd[4 * q + 0], acc[r]);
            acc[r] = fmaf(hv.y, wd[4 * q + 1], acc[r]);
            acc[r] = fmaf(hv.z, wd[4 * q + 2], acc[r]);
            acc[r] = fmaf(hv.w, wd[4 * q + 3], acc[r]);
        }
    }

    if (live) {
        #pragma unroll
        for (int r = 0; r < 8; r++)
            out[(tok0 + (size_t)(tg * 8 + r)) * VV + v] = acc[r];
    }
}

// =====================================================================
extern "C" void kernel_launch(void* const* d_in, const int* in_sizes, int n_in,
                              void* d_out, int out_size) {
    const int*   enc_ids = (const int*)  d_in[0];
    const int*   dec_ids = (const int*)  d_in[1];
    const float* embed   = (const float*)d_in[2];
    const float* enc_Wx  = (const float*)d_in[3];
    const float* enc_Wh  = (const float*)d_in[4];
    const float* enc_b   = (const float*)d_in[5];
    const float* dec_Wx  = (const float*)d_in[6];
    const float* dec_Wh  = (const float*)d_in[7];
    const float* dec_b   = (const float*)d_in[8];
    const float* dense_W = (const float*)d_in[9];
    const float* dense_b = (const float*)d_in[10];
    float* out = (float*)d_out;

    scan_kernel<<<BB / 2, 256>>>(enc_ids, dec_ids, embed,
                                 enc_Wx, enc_Wh, enc_b,
                                 dec_Wx, dec_Wh, dec_b);
    logits_kernel<<<(BB * SD) / 64, 256>>>(dense_W, dense_b, out);
}

// round 2
// speedup vs baseline: 1.0328x; 1.0328x over previous
#include <cuda_runtime.h>
#include <math.h>

// Problem constants
#define VV 27
#define EE 64
#define HH 128
#define BB 256
#define SE 512
#define SD 512

typedef unsigned long long ull;

// Scratch for decoder hidden states: [B, S_DEC, H] fp32 = 64 MB.
__device__ float g_dec_h[(size_t)BB * SD * HH];

// ---- packed fp32x2 helpers (sm_103a FFMA2 — not emitted by ptxas from C++) ----
__device__ __forceinline__ void ffma2(ull& d, ull a, ull b) {
    asm("fma.rn.f32x2 %0, %1, %2, %0;" : "+l"(d) : "l"(a), "l"(b));
}
__device__ __forceinline__ ull pack2(float x, float y) {
    ull r; asm("mov.b64 %0, {%1, %2};" : "=l"(r) : "f"(x), "f"(y)); return r;
}
__device__ __forceinline__ float2 unpack2(ull v) {
    float2 r; asm("mov.b64 {%0, %1}, %2;" : "=f"(r.x), "=f"(r.y) : "l"(v)); return r;
}

// Fast-but-accurate tanh: 1 - 2/(exp(2x)+1). ~5 ops, abs err ~1e-6.
__device__ __forceinline__ float fast_tanh(float x) {
    float e = __expf(x * 2.0f);
    return 1.0f - __fdividef(2.0f, e + 1.0f);
}

// =====================================================================
// Kernel 1: fused encoder+decoder scan.
// Grid: 128 CTAs x 256 threads; CTA owns 2 batch rows (independent
// named barriers). Thread j computes hidden unit j; Wh column j held
// in 64 packed u64 registers; inner dot = 64 FFMA2.
// =====================================================================
__global__ void __launch_bounds__(256, 1) scan_kernel(
    const int*   __restrict__ enc_ids, const int* __restrict__ dec_ids,
    const float* __restrict__ embed,
    const float* __restrict__ enc_Wx, const float* __restrict__ enc_Wh,
    const float* __restrict__ enc_b,
    const float* __restrict__ dec_Wx, const float* __restrict__ dec_Wh,
    const float* __restrict__ dec_b)
{
    __shared__ float tabE[VV][HH];                    // 13.5 KB
    __shared__ float tabD[VV][HH];                    // 13.5 KB
    __shared__ float emb_s[VV * EE];                  // 6.75 KB
    __shared__ __align__(16) float hbuf[2][2][HH];    // double-buffered h
    __shared__ int   idsE[2][SE];                     // 4 KB
    __shared__ int   idsD[2][SD];                     // 4 KB

    const int tid  = threadIdx.x;
    const int grp  = tid >> 7;
    const int j    = tid & (HH - 1);
    const int row0 = blockIdx.x * 2;
    const int row  = row0 + grp;

    // ---- stage embeddings + token ids ----
    for (int i = tid; i < VV * EE; i += 256) emb_s[i] = embed[i];
    for (int i = tid; i < SE; i += 256) {
        idsE[0][i] = enc_ids[(size_t)row0 * SE + i];
        idsE[1][i] = enc_ids[(size_t)(row0 + 1) * SE + i];
    }
    for (int i = tid; i < SD; i += 256) {
        idsD[0][i] = dec_ids[(size_t)row0 * SD + i];
        idsD[1][i] = dec_ids[(size_t)(row0 + 1) * SD + i];
    }
    __syncthreads();

    // ---- token tables: tab[v][h] = emb[v]@Wx[:,h] + b[h] ----
    for (int idx = tid; idx < VV * HH; idx += 256) {
        const int v = idx / HH;
        const int h = idx - v * HH;
        float sE = enc_b[h];
        float sD = dec_b[h];
        #pragma unroll 8
        for (int e = 0; e < EE; e++) {
            const float em = emb_s[v * EE + e];
            sE = fmaf(em, enc_Wx[e * HH + h], sE);
            sD = fmaf(em, dec_Wx[e * HH + h], sD);
        }
        tabE[v][h] = sE;
        tabD[v][h] = sD;
    }

    hbuf[0][grp][j] = 0.0f;
    __syncthreads();

    // ---- encoder phase: packed Wh column in 64 u64 regs ----
    ull w2[HH / 2];
    #pragma unroll
    for (int k = 0; k < HH / 2; k++)
        w2[k] = pack2(enc_Wh[(2 * k) * HH + j], enc_Wh[(2 * k + 1) * HH + j]);

    int cur = 0;
    for (int t = 0; t < SE; t++) {
        const ulonglong2* hq = (const ulonglong2*)hbuf[cur][grp];
        ull a0 = 0, a1 = 0, a2 = 0, a3 = 0;   // 0.0f pairs
        #pragma unroll
        for (int q = 0; q < HH / 4; q += 2) {
            ulonglong2 h0 = hq[q];
            ulonglong2 h1 = hq[q + 1];
            ffma2(a0, h0.x, w2[2 * q + 0]);
            ffma2(a1, h0.y, w2[2 * q + 1]);
            ffma2(a2, h1.x, w2[2 * q + 2]);
            ffma2(a3, h1.y, w2[2 * q + 3]);
        }
        float2 s0 = unpack2(a0), s1 = unpack2(a1), s2 = unpack2(a2), s3 = unpack2(a3);
        float dot = ((s0.x + s0.y) + (s1.x + s1.y)) + ((s2.x + s2.y) + (s3.x + s3.y));
        const int id = idsE[grp][t];
        const float hn = fast_tanh(dot + tabE[id][j]);
        hbuf[cur ^ 1][grp][j] = hn;
        asm volatile("bar.sync %0, 128;" :: "r"(grp + 1) : "memory");
        cur ^= 1;
    }

    // ---- decoder phase ----
    #pragma unroll
    for (int k = 0; k < HH / 2; k++)
        w2[k] = pack2(dec_Wh[(2 * k) * HH + j], dec_Wh[(2 * k + 1) * HH + j]);

    float* outrow = g_dec_h + (size_t)row * SD * HH;
    for (int t = 0; t < SD; t++) {
        const ulonglong2* hq = (const ulonglong2*)hbuf[cur][grp];
        ull a0 = 0, a1 = 0, a2 = 0, a3 = 0;
        #pragma unroll
        for (int q = 0; q < HH / 4; q += 2) {
            ulonglong2 h0 = hq[q];
            ulonglong2 h1 = hq[q + 1];
            ffma2(a0, h0.x, w2[2 * q + 0]);
            ffma2(a1, h0.y, w2[2 * q + 1]);
            ffma2(a2, h1.x, w2[2 * q + 2]);
            ffma2(a3, h1.y, w2[2 * q + 3]);
        }
        float2 s0 = unpack2(a0), s1 = unpack2(a1), s2 = unpack2(a2), s3 = unpack2(a3);
        float dot = ((s0.x + s0.y) + (s1.x + s1.y)) + ((s2.x + s2.y) + (s3.x + s3.y));
        const int id = idsD[grp][t];
        const float hn = fast_tanh(dot + tabD[id][j]);
        hbuf[cur ^ 1][grp][j] = hn;
        outrow[t * HH + j] = hn;
        asm volatile("bar.sync %0, 128;" :: "r"(grp + 1) : "memory");
        cur ^= 1;
    }
}

// =====================================================================
// Kernel 2: logits = dec_h @ dense_W + dense_b.
// [131072,128] x [128,27->32pad]. 256 thr: v=tid&31, 8 tokens each.
// W packed (k-pairs) in smem; FFMA2 inner loop; low regs -> high occ.
// =====================================================================
__global__ void __launch_bounds__(256) logits_kernel(
    const float* __restrict__ dense_W, const float* __restrict__ dense_b,
    float* __restrict__ out)
{
    __shared__ __align__(16) float hs[64 * HH];   // 32 KB
    __shared__ ull w2s[(HH / 2) * 32];            // 16 KB: [pair p][v]

    const int tid = threadIdx.x;
    const int v   = tid & 31;
    const int tg  = tid >> 5;
    const size_t tok0 = (size_t)blockIdx.x * 64;

    // stage h tile (float4 coalesced)
    const float4* hsrc = (const float4*)(g_dec_h + tok0 * HH);
    float4* hdst = (float4*)hs;
    #pragma unroll
    for (int i = 0; i < 8; i++) hdst[tid + 256 * i] = hsrc[tid + 256 * i];

    // stage packed W: w2s[p*32+v] = (W[2p][v], W[2p+1][v]); pad v>=27 with 0
    for (int p = tg; p < HH / 2; p += 8) {
        float wa = (v < VV) ? dense_W[(2 * p) * VV + v] : 0.0f;
        float wb = (v < VV) ? dense_W[(2 * p + 1) * VV + v] : 0.0f;
        w2s[p * 32 + v] = pack2(wa, wb);
    }
    __syncthreads();

    ull acc[8];
    #pragma unroll
    for (int r = 0; r < 8; r++) acc[r] = 0;

    #pragma unroll
    for (int q = 0; q < HH / 4; q++) {
        const ull wA = w2s[(2 * q + 0) * 32 + v];
        const ull wB = w2s[(2 * q + 1) * 32 + v];
        #pragma unroll
        for (int r = 0; r < 8; r++) {
            const ulonglong2 hv =
                ((const ulonglong2*)(hs + (tg * 8 + r) * HH))[q];  // broadcast
            ffma2(acc[r], hv.x, wA);
            ffma2(acc[r], hv.y, wB);
        }
    }

    if (v < VV) {
        const float bias = dense_b[v];
        #pragma unroll
        for (int r = 0; r < 8; r++) {
            float2 s = unpack2(acc[r]);
            out[(tok0 + (size_t)(tg * 8 + r)) * VV + v] = s.x + s.y + bias;
        }
    }
}

// =====================================================================
extern "C" void kernel_launch(void* const* d_in, const int* in_sizes, int n_in,
                              void* d_out, int out_size) {
    const int*   enc_ids = (const int*)  d_in[0];
    const int*   dec_ids = (const int*)  d_in[1];
    const float* embed   = (const float*)d_in[2];
    const float* enc_Wx  = (const float*)d_in[3];
    const float* enc_Wh  = (const float*)d_in[4];
    const float* enc_b   = (const float*)d_in[5];
    const float* dec_Wx  = (const float*)d_in[6];
    const float* dec_Wh  = (const float*)d_in[7];
    const float* dec_b   = (const float*)d_in[8];
    const float* dense_W = (const float*)d_in[9];
    const float* dense_b = (const float*)d_in[10];
    float* out = (float*)d_out;

    scan_kernel<<<BB / 2, 256>>>(enc_ids, dec_ids, embed,
                                 enc_Wx, enc_Wh, enc_b,
                                 dec_Wx, dec_Wh, dec_b);
    logits_kernel<<<(BB * SD) / 64, 256>>>(dense_W, dense_b, out);
}